// round 8
// baseline (speedup 1.0000x reference)
#include <cuda_runtime.h>
#include <cstdint>

constexpr int Bc = 256;   // batch
constexpr int Cc = 128;   // channels
constexpr int Hc = 1024;  // hidden
constexpr int Ic = 512;   // input features
constexpr int Oc = 128;   // output features

constexpr int TILEW  = 128 * 20;        // words per (A or B) stage tile (16 data + 4 pad / row)
constexpr int STAGEW = 2 * TILEW;       // A tile then B tile
constexpr int SMEM_BYTES = 4 * STAGEW * 4;   // 81920 B (4 stages)

// hidden activations scratch: [b][c][h]  (128 MB, static device global)
__device__ float g_h[(size_t)Bc * Cc * Hc];

__device__ __forceinline__ uint32_t s2u(const void* p) {
    uint32_t a;
    asm("{ .reg .u64 t; cvta.to.shared.u64 t, %1; cvt.u32.u64 %0, t; }" : "=r"(a) : "l"(p));
    return a;
}
__device__ __forceinline__ void cp16(uint32_t dst, const float* src) {
    asm volatile("cp.async.cg.shared.global [%0], [%1], 16;" :: "r"(dst), "l"(src));
}
__device__ __forceinline__ void mma8(float4& d,
                                     uint32_t a0, uint32_t a1, uint32_t a2, uint32_t a3,
                                     uint32_t b0, uint32_t b1) {
    asm volatile(
        "mma.sync.aligned.m16n8k8.row.col.f32.tf32.tf32.f32 "
        "{%0,%1,%2,%3}, {%4,%5,%6,%7}, {%8,%9}, {%0,%1,%2,%3};"
        : "+f"(d.x), "+f"(d.y), "+f"(d.z), "+f"(d.w)
        : "r"(a0), "r"(a1), "r"(a2), "r"(a3), "r"(b0), "r"(b1));
}
// fp32 bits -> tf32 round-to-nearest (HMMA drops low 13 bits; +0x1000 = RN)
__device__ __forceinline__ uint32_t rn(uint32_t u) { return u + 0x1000u; }

// ---------------------------------------------------------------------------
// 4-stage cp.async pipelined tf32 GEMM, 128x128 CTA tile, 128 threads,
// 4 warps each owning a 64x64 warp tile (acc[4][8] float4).
// Loader: thread t handles A row t and B row t (4 cp16 each per stage).
// ---------------------------------------------------------------------------
#define CP_STAGE(S)                                                              \
    do {                                                                         \
        const int _sl = (S) & 3;                                                 \
        const uint32_t _aw = sA + (uint32_t)(_sl * STAGEW) * 4;                  \
        const uint32_t _bw = _aw + TILEW * 4;                                    \
        cp16(_aw,      AGc + (S) * 16);                                          \
        cp16(_aw + 16, AGc + (S) * 16 + 4);                                      \
        cp16(_aw + 32, AGc + (S) * 16 + 8);                                      \
        cp16(_aw + 48, AGc + (S) * 16 + 12);                                     \
        cp16(_bw,      BGc + (S) * 16);                                          \
        cp16(_bw + 16, BGc + (S) * 16 + 4);                                      \
        cp16(_bw + 32, BGc + (S) * 16 + 8);                                      \
        cp16(_bw + 48, BGc + (S) * 16 + 12);                                     \
    } while (0)

#define GEMM_MAINLOOP(KDIM)                                                      \
    float4 acc[4][8];                                                            \
    _Pragma("unroll") for (int t = 0; t < 4; t++)                                \
        _Pragma("unroll") for (int u = 0; u < 8; u++)                            \
            acc[t][u] = make_float4(0.f, 0.f, 0.f, 0.f);                         \
    const int NIT = (KDIM) / 16;                                                 \
    _Pragma("unroll") for (int s = 0; s < 3; s++) {                              \
        CP_STAGE(s);                                                             \
        asm volatile("cp.async.commit_group;" ::: "memory");                     \
    }                                                                            \
    for (int i = 0; i < NIT; i++) {                                              \
        const int sl = i & 3;                                                    \
        asm volatile("cp.async.wait_group 2;" ::: "memory");                     \
        __syncthreads();                                                         \
        if (i + 3 < NIT) CP_STAGE(i + 3);                                        \
        asm volatile("cp.async.commit_group;" ::: "memory");                     \
        const uint32_t* Afp = smw + sl * STAGEW + faoff;                         \
        const uint32_t* Bfp = smw + sl * STAGEW + TILEW + fboff;                 \
        _Pragma("unroll") for (int kk = 0; kk < 16; kk += 8) {                   \
            uint32_t a[4][4], b[8][2];                                           \
            _Pragma("unroll") for (int t = 0; t < 4; t++) {                      \
                a[t][0] = rn(Afp[(t * 16) * 20 + kk]);                           \
                a[t][1] = rn(Afp[(t * 16 + 8) * 20 + kk]);                       \
                a[t][2] = rn(Afp[(t * 16) * 20 + kk + 4]);                       \
                a[t][3] = rn(Afp[(t * 16 + 8) * 20 + kk + 4]);                   \
            }                                                                    \
            _Pragma("unroll") for (int u = 0; u < 8; u++) {                      \
                b[u][0] = rn(Bfp[(u * 8) * 20 + kk]);                            \
                b[u][1] = rn(Bfp[(u * 8) * 20 + kk + 4]);                        \
            }                                                                    \
            _Pragma("unroll") for (int t = 0; t < 4; t++)                        \
                _Pragma("unroll") for (int u = 0; u < 8; u++)                    \
                    mma8(acc[t][u], a[t][0], a[t][1], a[t][2], a[t][3],          \
                         b[u][0], b[u][1]);                                      \
        }                                                                        \
    }

// ---------------------------------------------------------------------------
// Kernel 1: h[b, c, :] = relu(X_c @ W1_c^T + b1_c)
// ---------------------------------------------------------------------------
__global__ __launch_bounds__(128, 2)
void mlp_k1(const float* __restrict__ x, const float* __restrict__ w1,
            const float* __restrict__ b1) {
    extern __shared__ uint32_t smw[];
    const int c = blockIdx.z, m0 = blockIdx.y * 128, n0 = blockIdx.x * 128;

    const int tid = threadIdx.x, l = tid & 31, w = tid >> 5;
    const int wm = (w & 1) * 64, wn = (w >> 1) * 64;
    const int lr4 = l >> 2, lc4 = l & 3;

    const float* AGc = x  + ((size_t)(m0 + tid) * Cc + c) * Ic;
    const float* BGc = w1 + ((size_t)c * Hc + n0 + tid) * Ic;
    const uint32_t sA = s2u(smw) + (uint32_t)(tid * 20) * 4;
    const int faoff = (wm + lr4) * 20 + lc4;
    const int fboff = (wn + lr4) * 20 + lc4;

    GEMM_MAINLOOP(Ic)

    #pragma unroll
    for (int t = 0; t < 4; t++) {
        const int r0 = m0 + wm + t * 16 + lr4;
        #pragma unroll
        for (int u = 0; u < 8; u++) {
            const int n = n0 + wn + u * 8 + lc4 * 2;
            const float2 bb = *(const float2*)&b1[c * Hc + n];
            float2 lo = {fmaxf(acc[t][u].x + bb.x, 0.f),
                         fmaxf(acc[t][u].y + bb.y, 0.f)};
            float2 hi = {fmaxf(acc[t][u].z + bb.x, 0.f),
                         fmaxf(acc[t][u].w + bb.y, 0.f)};
            *(float2*)&g_h[((size_t)r0 * Cc + c) * Hc + n]       = lo;
            *(float2*)&g_h[((size_t)(r0 + 8) * Cc + c) * Hc + n] = hi;
        }
    }
}

// ---------------------------------------------------------------------------
// Kernel 2: out[b, :, c] = h[b, c, :] @ W2_c^T + b2_c   (output (B, O, C))
// ---------------------------------------------------------------------------
__global__ __launch_bounds__(128, 2)
void mlp_k2(const float* __restrict__ w2, const float* __restrict__ b2,
            float* __restrict__ out) {
    extern __shared__ uint32_t smw[];
    const int c = blockIdx.z, m0 = blockIdx.y * 128, n0 = 0;

    const int tid = threadIdx.x, l = tid & 31, w = tid >> 5;
    const int wm = (w & 1) * 64, wn = (w >> 1) * 64;
    const int lr4 = l >> 2, lc4 = l & 3;

    const float* AGc = g_h + ((size_t)(m0 + tid) * Cc + c) * Hc;
    const float* BGc = w2  + ((size_t)c * Oc + n0 + tid) * Hc;
    const uint32_t sA = s2u(smw) + (uint32_t)(tid * 20) * 4;
    const int faoff = (wm + lr4) * 20 + lc4;
    const int fboff = (wn + lr4) * 20 + lc4;

    GEMM_MAINLOOP(Hc)

    #pragma unroll
    for (int t = 0; t < 4; t++) {
        const int r0 = m0 + wm + t * 16 + lr4;
        #pragma unroll
        for (int u = 0; u < 8; u++) {
            const int n = n0 + wn + u * 8 + lc4 * 2;
            const float2 bb = *(const float2*)&b2[c * Oc + n];
            out[((size_t)r0 * Oc + n) * Cc + c]           = acc[t][u].x + bb.x;
            out[((size_t)r0 * Oc + n + 1) * Cc + c]       = acc[t][u].y + bb.y;
            out[((size_t)(r0 + 8) * Oc + n) * Cc + c]     = acc[t][u].z + bb.x;
            out[((size_t)(r0 + 8) * Oc + n + 1) * Cc + c] = acc[t][u].w + bb.y;
        }
    }
}

extern "C" void kernel_launch(void* const* d_in, const int* in_sizes, int n_in,
                              void* d_out, int out_size) {
    const float* x  = (const float*)d_in[0];
    const float* w1 = (const float*)d_in[1];
    const float* b1 = (const float*)d_in[2];
    const float* w2 = (const float*)d_in[3];
    const float* b2 = (const float*)d_in[4];
    float* out = (float*)d_out;

    static bool attr_set = false;
    if (!attr_set) {
        cudaFuncSetAttribute(mlp_k1, cudaFuncAttributeMaxDynamicSharedMemorySize, SMEM_BYTES);
        cudaFuncSetAttribute(mlp_k2, cudaFuncAttributeMaxDynamicSharedMemorySize, SMEM_BYTES);
        attr_set = true;
    }

    dim3 block(128);
    dim3 grid1(Hc / 128, Bc / 128, Cc);   // (8, 2, 128)
    dim3 grid2(1,        Bc / 128, Cc);   // (1, 2, 128)
    mlp_k1<<<grid1, block, SMEM_BYTES>>>(x, w1, b1);
    mlp_k2<<<grid2, block, SMEM_BYTES>>>(w2, b2, out);
}

// round 9
// speedup vs baseline: 1.9617x; 1.9617x over previous
#include <cuda_runtime.h>
#include <cstdint>

constexpr int Bc = 256;   // batch
constexpr int Cc = 128;   // channels
constexpr int Hc = 1024;  // hidden
constexpr int Ic = 512;   // input features
constexpr int Oc = 128;   // output features

constexpr int TILEW  = 128 * 20;        // words per (A or B) stage tile (16 data + 4 pad / row)
constexpr int STAGEW = 2 * TILEW;       // A tile then B tile
constexpr int SMEM_BYTES = 4 * STAGEW * 4;   // 81920 B (4 stages)

// hidden activations scratch: [b][c][h]  (128 MB, static device global)
__device__ float g_h[(size_t)Bc * Cc * Hc];

__device__ __forceinline__ uint32_t s2u(const void* p) {
    uint32_t a;
    asm("{ .reg .u64 t; cvta.to.shared.u64 t, %1; cvt.u32.u64 %0, t; }" : "=r"(a) : "l"(p));
    return a;
}
__device__ __forceinline__ void cp16(uint32_t dst, const float* src) {
    asm volatile("cp.async.cg.shared.global [%0], [%1], 16;" :: "r"(dst), "l"(src));
}
__device__ __forceinline__ void mma8(float4& d,
                                     uint32_t a0, uint32_t a1, uint32_t a2, uint32_t a3,
                                     uint32_t b0, uint32_t b1) {
    asm volatile(
        "mma.sync.aligned.m16n8k8.row.col.f32.tf32.tf32.f32 "
        "{%0,%1,%2,%3}, {%4,%5,%6,%7}, {%8,%9}, {%0,%1,%2,%3};"
        : "+f"(d.x), "+f"(d.y), "+f"(d.z), "+f"(d.w)
        : "r"(a0), "r"(a1), "r"(a2), "r"(a3), "r"(b0), "r"(b1));
}
// fp32 bits -> tf32 round-to-nearest (HMMA drops low 13 bits; +0x1000 = RN)
__device__ __forceinline__ uint32_t rn(uint32_t u) { return u + 0x1000u; }

// ---------------------------------------------------------------------------
// 4-stage cp.async pipelined tf32 GEMM, 128x128 CTA tile, 512 threads,
// 16 warps each owning a 32x32 warp tile (acc[2][4] float4 = 32 regs).
// Loader: thread t covers (row = t>>2, koff = (t&3)*4): 1 cp16 A + 1 cp16 B.
// ---------------------------------------------------------------------------
#define CP_STAGE(S)                                                              \
    do {                                                                         \
        const int _sl = (S) & 3;                                                 \
        const uint32_t _aw = sA + (uint32_t)(_sl * STAGEW) * 4;                  \
        cp16(_aw,              AGc + (S) * 16);                                  \
        cp16(_aw + TILEW * 4,  BGc + (S) * 16);                                  \
    } while (0)

#define GEMM_MAINLOOP(KDIM)                                                      \
    float4 acc[2][4];                                                            \
    _Pragma("unroll") for (int t = 0; t < 2; t++)                                \
        _Pragma("unroll") for (int u = 0; u < 4; u++)                            \
            acc[t][u] = make_float4(0.f, 0.f, 0.f, 0.f);                         \
    const int NIT = (KDIM) / 16;                                                 \
    _Pragma("unroll") for (int s = 0; s < 3; s++) {                              \
        CP_STAGE(s);                                                             \
        asm volatile("cp.async.commit_group;" ::: "memory");                     \
    }                                                                            \
    for (int i = 0; i < NIT; i++) {                                              \
        const int sl = i & 3;                                                    \
        asm volatile("cp.async.wait_group 2;" ::: "memory");                     \
        __syncthreads();                                                         \
        if (i + 3 < NIT) CP_STAGE(i + 3);                                        \
        asm volatile("cp.async.commit_group;" ::: "memory");                     \
        const uint32_t* Afp = smw + sl * STAGEW + faoff;                         \
        const uint32_t* Bfp = smw + sl * STAGEW + TILEW + fboff;                 \
        _Pragma("unroll") for (int kk = 0; kk < 16; kk += 8) {                   \
            uint32_t a[2][4], b[4][2];                                           \
            _Pragma("unroll") for (int t = 0; t < 2; t++) {                      \
                a[t][0] = rn(Afp[(t * 16) * 20 + kk]);                           \
                a[t][1] = rn(Afp[(t * 16 + 8) * 20 + kk]);                       \
                a[t][2] = rn(Afp[(t * 16) * 20 + kk + 4]);                       \
                a[t][3] = rn(Afp[(t * 16 + 8) * 20 + kk + 4]);                   \
            }                                                                    \
            _Pragma("unroll") for (int u = 0; u < 4; u++) {                      \
                b[u][0] = rn(Bfp[(u * 8) * 20 + kk]);                            \
                b[u][1] = rn(Bfp[(u * 8) * 20 + kk + 4]);                        \
            }                                                                    \
            _Pragma("unroll") for (int t = 0; t < 2; t++)                        \
                _Pragma("unroll") for (int u = 0; u < 4; u++)                    \
                    mma8(acc[t][u], a[t][0], a[t][1], a[t][2], a[t][3],          \
                         b[u][0], b[u][1]);                                      \
        }                                                                        \
    }

// ---------------------------------------------------------------------------
// Kernel 1: h[b, c, :] = relu(X_c @ W1_c^T + b1_c)
// ---------------------------------------------------------------------------
__global__ __launch_bounds__(512, 2)
void mlp_k1(const float* __restrict__ x, const float* __restrict__ w1,
            const float* __restrict__ b1) {
    extern __shared__ uint32_t smw[];
    const int c = blockIdx.z, m0 = blockIdx.y * 128, n0 = blockIdx.x * 128;

    const int tid = threadIdx.x, l = tid & 31, w = tid >> 5;
    const int wm = (w & 3) * 32, wn = (w >> 2) * 32;
    const int lr4 = l >> 2, lc4 = l & 3;
    const int row = tid >> 2, koff = (tid & 3) * 4;

    const float* AGc = x  + ((size_t)(m0 + row) * Cc + c) * Ic + koff;
    const float* BGc = w1 + ((size_t)c * Hc + n0 + row) * Ic + koff;
    const uint32_t sA = s2u(smw) + (uint32_t)(row * 20 + koff) * 4;
    const int faoff = (wm + lr4) * 20 + lc4;
    const int fboff = (wn + lr4) * 20 + lc4;

    GEMM_MAINLOOP(Ic)

    #pragma unroll
    for (int t = 0; t < 2; t++) {
        const int r0 = m0 + wm + t * 16 + lr4;
        #pragma unroll
        for (int u = 0; u < 4; u++) {
            const int n = n0 + wn + u * 8 + lc4 * 2;
            const float2 bb = *(const float2*)&b1[c * Hc + n];
            float2 lo = {fmaxf(acc[t][u].x + bb.x, 0.f),
                         fmaxf(acc[t][u].y + bb.y, 0.f)};
            float2 hi = {fmaxf(acc[t][u].z + bb.x, 0.f),
                         fmaxf(acc[t][u].w + bb.y, 0.f)};
            *(float2*)&g_h[((size_t)r0 * Cc + c) * Hc + n]       = lo;
            *(float2*)&g_h[((size_t)(r0 + 8) * Cc + c) * Hc + n] = hi;
        }
    }
}

// ---------------------------------------------------------------------------
// Kernel 2: out[b, :, c] = h[b, c, :] @ W2_c^T + b2_c   (output (B, O, C))
// ---------------------------------------------------------------------------
__global__ __launch_bounds__(512, 2)
void mlp_k2(const float* __restrict__ w2, const float* __restrict__ b2,
            float* __restrict__ out) {
    extern __shared__ uint32_t smw[];
    const int c = blockIdx.z, m0 = blockIdx.y * 128, n0 = 0;

    const int tid = threadIdx.x, l = tid & 31, w = tid >> 5;
    const int wm = (w & 3) * 32, wn = (w >> 2) * 32;
    const int lr4 = l >> 2, lc4 = l & 3;
    const int row = tid >> 2, koff = (tid & 3) * 4;

    const float* AGc = g_h + ((size_t)(m0 + row) * Cc + c) * Hc + koff;
    const float* BGc = w2  + ((size_t)c * Oc + n0 + row) * Hc + koff;
    const uint32_t sA = s2u(smw) + (uint32_t)(row * 20 + koff) * 4;
    const int faoff = (wm + lr4) * 20 + lc4;
    const int fboff = (wn + lr4) * 20 + lc4;

    GEMM_MAINLOOP(Hc)

    #pragma unroll
    for (int t = 0; t < 2; t++) {
        const int r0 = m0 + wm + t * 16 + lr4;
        #pragma unroll
        for (int u = 0; u < 4; u++) {
            const int n = n0 + wn + u * 8 + lc4 * 2;
            const float2 bb = *(const float2*)&b2[c * Oc + n];
            out[((size_t)r0 * Oc + n) * Cc + c]           = acc[t][u].x + bb.x;
            out[((size_t)r0 * Oc + n + 1) * Cc + c]       = acc[t][u].y + bb.y;
            out[((size_t)(r0 + 8) * Oc + n) * Cc + c]     = acc[t][u].z + bb.x;
            out[((size_t)(r0 + 8) * Oc + n + 1) * Cc + c] = acc[t][u].w + bb.y;
        }
    }
}

extern "C" void kernel_launch(void* const* d_in, const int* in_sizes, int n_in,
                              void* d_out, int out_size) {
    const float* x  = (const float*)d_in[0];
    const float* w1 = (const float*)d_in[1];
    const float* b1 = (const float*)d_in[2];
    const float* w2 = (const float*)d_in[3];
    const float* b2 = (const float*)d_in[4];
    float* out = (float*)d_out;

    static bool attr_set = false;
    if (!attr_set) {
        cudaFuncSetAttribute(mlp_k1, cudaFuncAttributeMaxDynamicSharedMemorySize, SMEM_BYTES);
        cudaFuncSetAttribute(mlp_k2, cudaFuncAttributeMaxDynamicSharedMemorySize, SMEM_BYTES);
        attr_set = true;
    }

    dim3 block(512);
    dim3 grid1(Hc / 128, Bc / 128, Cc);   // (8, 2, 128)
    dim3 grid2(1,        Bc / 128, Cc);   // (1, 2, 128)
    mlp_k1<<<grid1, block, SMEM_BYTES>>>(x, w1, b1);
    mlp_k2<<<grid2, block, SMEM_BYTES>>>(w2, b2, out);
}